// round 7
// baseline (speedup 1.0000x reference)
#include <cuda_runtime.h>
#include <cuda_bf16.h>
#include <cstdint>
#include <math.h>

#define BB 8
#define SS 1024
#define EE 1024
#define HH 8
#define HD 128
#define MM (BB*SS)

// Scratch (allocation-free: __device__ globals), all split-bf16 hi/lo planes
__device__ __nv_bfloat16 g_wnh[4L * EE * EE], g_wnl[4L * EE * EE]; // weights
__device__ __nv_bfloat16 g_xh[(long)MM * EE], g_xl[(long)MM * EE]; // query
__device__ __nv_bfloat16 g_ph[2L * MM * EE],  g_pl[2L * MM * EE];  // Q,K
__device__ __nv_bfloat16 g_vth[(long)MM * EE], g_vtl[(long)MM * EE]; // V^T
__device__ float g_sc[(long)BB * HH * SS * SS];                    // scores fp32
__device__ __nv_bfloat16 g_ah[(long)BB * HH * SS * SS];            // attn hi
__device__ __nv_bfloat16 g_al[(long)BB * HH * SS * SS];            // attn lo
__device__ __nv_bfloat16 g_ovh[(long)MM * EE], g_ovl[(long)MM * EE]; // attn out

// ===========================================================================
// helpers
// ===========================================================================
__device__ __forceinline__ uint32_t smem_u32(const void* p) {
    uint32_t a;
    asm("{ .reg .u64 t; cvta.to.shared.u64 t, %1; cvt.u32.u64 %0, t; }"
        : "=r"(a) : "l"(p));
    return a;
}
__device__ __forceinline__ void ldmat4(uint32_t* r, uint32_t addr) {
    asm volatile("ldmatrix.sync.aligned.m8n8.x4.shared.b16 {%0,%1,%2,%3}, [%4];"
                 : "=r"(r[0]), "=r"(r[1]), "=r"(r[2]), "=r"(r[3]) : "r"(addr));
}
__device__ __forceinline__ void mma16816(float* c, const uint32_t* a, const uint32_t* b) {
    asm volatile(
        "mma.sync.aligned.m16n8k16.row.col.f32.bf16.bf16.f32 "
        "{%0,%1,%2,%3}, {%4,%5,%6,%7}, {%8,%9}, {%0,%1,%2,%3};"
        : "+f"(c[0]), "+f"(c[1]), "+f"(c[2]), "+f"(c[3])
        : "r"(a[0]), "r"(a[1]), "r"(a[2]), "r"(a[3]), "r"(b[0]), "r"(b[1]));
}
__device__ __forceinline__ void cpa16(uint32_t dst, const void* src) {
    asm volatile("cp.async.cg.shared.global [%0], [%1], 16;"
                 :: "r"(dst), "l"(src) : "memory");
}
__device__ __forceinline__ void cp_commit() {
    asm volatile("cp.async.commit_group;" ::: "memory");
}
template<int N>
__device__ __forceinline__ void cp_wait() {
    asm volatile("cp.async.wait_group %0;" :: "n"(N) : "memory");
}
__device__ __forceinline__ void split2(float x, float y,
                                       __nv_bfloat162& hi, __nv_bfloat162& lo) {
    hi.x = __float2bfloat16(x); hi.y = __float2bfloat16(y);
    lo.x = __float2bfloat16(x - __bfloat162float(hi.x));
    lo.y = __float2bfloat16(y - __bfloat162float(hi.y));
}

// swizzled byte offset of (row, elem) in a packed [rows][32] bf16 tile plane
__device__ __forceinline__ uint32_t tswz(int r, int e) {
    return (uint32_t)(r * 64 + ((((e >> 3) ^ (r >> 1)) & 3) << 4) + (e & 7) * 2);
}

// ===========================================================================
// Weight normalization -> split bf16 planes
// ===========================================================================
__global__ void norm_w_kernel(const float* __restrict__ qw,
                              const float* __restrict__ kw,
                              const float* __restrict__ vw,
                              const float* __restrict__ ow,
                              const float* __restrict__ gain) {
    int mat = blockIdx.y;
    int row = blockIdx.x;
    const float* w = (mat == 0) ? qw : (mat == 1) ? kw : (mat == 2) ? vw : ow;
    const float* wr = w + (long)row * EE;
    __shared__ float red[256];
    float s = 0.f;
    for (int i = threadIdx.x; i < EE; i += 256) { float v = wr[i]; s += v * v; }
    red[threadIdx.x] = s; __syncthreads();
    for (int o = 128; o > 0; o >>= 1) {
        if (threadIdx.x < o) red[threadIdx.x] += red[threadIdx.x + o];
        __syncthreads();
    }
    float n = sqrtf(red[0]);
    float scale = gain[0] / (32.0f * 1e-4f + n);
    long base = (long)mat * EE * EE + (long)row * EE;
    for (int i = threadIdx.x * 2; i < EE; i += 512) {
        __nv_bfloat162 hi, lo;
        split2(wr[i] * scale, wr[i + 1] * scale, hi, lo);
        *(__nv_bfloat162*)(g_wnh + base + i) = hi;
        *(__nv_bfloat162*)(g_wnl + base + i) = lo;
    }
}

// ===========================================================================
// query fp32 -> split bf16 planes
// ===========================================================================
__global__ void convert_x_kernel(const float* __restrict__ x) {
    long i = ((long)blockIdx.x * 256 + threadIdx.x) * 4;
    float4 v = *(const float4*)(x + i);
    __nv_bfloat162 h0, l0, h1, l1;
    split2(v.x, v.y, h0, l0);
    split2(v.z, v.w, h1, l1);
    *(__nv_bfloat162*)(g_xh + i) = h0; *(__nv_bfloat162*)(g_xh + i + 2) = h1;
    *(__nv_bfloat162*)(g_xl + i) = l0; *(__nv_bfloat162*)(g_xl + i + 2) = l1;
}

// ===========================================================================
// bf16 split GEMM: D[M,N] = (Ah+Al)[M,K] @ (Bh+Bl)[N,K]^T, 3 passes
// (AhBh + AlBh + AhBl). CTA tile 256x128, 8 warps (4x2) of 64x64, BK=32,
// 2-stage cp.async pipeline, packed 64B rows + XOR chunk swizzle.
// MODE 0: C0 = fp32 acc
// MODE 1: split write: C0/C1 = hi/lo bf16 planes
// MODE 2: C0 = (acc + X) / sqrt(2), fp32
// MODE 3: transpose split write vt[b][h][d][s], smem-staged coalesced
// ===========================================================================
#define STG_BYTES 49152           // Ah 16K | Al 16K | Bh 8K | Bl 8K
#define SMEM_BYTES (2*STG_BYTES)  // 98304

template<int MODE>
__global__ __launch_bounds__(256, 1) void mma_gemm(
    const __nv_bfloat16* __restrict__ Ah, const __nv_bfloat16* __restrict__ Al,
    long sA1, long sA2, int lda,
    const __nv_bfloat16* __restrict__ Bh, const __nv_bfloat16* __restrict__ Bl,
    long sB1, long sB2, int ldb,
    void* C0v, void* C1v, long sC1, long sC2, int ldc,
    const float* __restrict__ X, int ldx,
    int Kr, int zdiv)
{
    extern __shared__ char smp[];
    const uint32_t smb = smem_u32(smp);

    const int tid = threadIdx.x;
    const int lane = tid & 31, wid = tid >> 5;
    const int wm = wid & 3, wn = wid >> 2;   // warp tile (wm*64, wn*64)

    int z = blockIdx.z;
    int zb = z / zdiv, zh = z - zb * zdiv;
    Ah += zb * sA1 + zh * sA2;  Al += zb * sA1 + zh * sA2;
    Bh += zb * sB1 + zh * sB2;  Bl += zb * sB1 + zh * sB2;
    const long coff = zb * sC1 + zh * sC2;
    const long bm = (long)blockIdx.y * 256;
    const long bn = (long)blockIdx.x * 128;

    const int lrow = tid >> 1;          // 0..127
    const int lc0 = (tid & 1) * 2;      // first of 2 16B chunks
    const uint32_t lsw = (uint32_t)((lrow >> 1) & 3);   // same for lrow+128

    const __nv_bfloat16* gAh0 = Ah + (bm + lrow) * (long)lda;
    const __nv_bfloat16* gAh1 = gAh0 + 128L * lda;
    const __nv_bfloat16* gAl0 = Al + (bm + lrow) * (long)lda;
    const __nv_bfloat16* gAl1 = gAl0 + 128L * lda;
    const __nv_bfloat16* gBh = Bh + (bn + lrow) * (long)ldb;
    const __nv_bfloat16* gBl = Bl + (bn + lrow) * (long)ldb;

    float acc[4][8][4];
    #pragma unroll
    for (int i = 0; i < 4; i++)
        #pragma unroll
        for (int j = 0; j < 8; j++)
            #pragma unroll
            for (int q = 0; q < 4; q++) acc[i][j][q] = 0.f;

    const int cpp = Kr >> 5;

    auto issue = [&](int chunk) {
        const uint32_t base = smb + (chunk & 1) * STG_BYTES;
        const int k0 = chunk << 5;
        #pragma unroll
        for (int j = 0; j < 2; j++) {
            int c = lc0 + j;
            uint32_t off = (uint32_t)(lrow * 64) + (((uint32_t)c ^ lsw) << 4);
            cpa16(base + off,                 gAh0 + k0 + c * 8);
            cpa16(base + off + 8192,          gAh1 + k0 + c * 8);
            cpa16(base + 16384 + off,         gAl0 + k0 + c * 8);
            cpa16(base + 16384 + off + 8192,  gAl1 + k0 + c * 8);
            cpa16(base + 32768 + off,         gBh + k0 + c * 8);
            cpa16(base + 40960 + off,         gBl + k0 + c * 8);
        }
    };

    issue(0); cp_commit();
    issue(1); cp_commit();

    const int r16 = lane & 15, kh8 = (lane >> 4) * 8;
    const int arow = wm * 64 + r16;
    const int brow = wn * 64 + r16;

    for (int kc = 0; kc < cpp; ++kc) {
        cp_wait<1>();
        __syncthreads();

        const uint32_t sb = smb + (kc & 1) * STG_BYTES;
        #pragma unroll
        for (int k16 = 0; k16 < 32; k16 += 16) {
            const int e = k16 + kh8;
            uint32_t ah[4][4], bh[8][2];
            #pragma unroll
            for (int mt = 0; mt < 4; mt++)
                ldmat4(ah[mt], sb + tswz(arow + mt * 16, e));
            #pragma unroll
            for (int nt4 = 0; nt4 < 4; nt4++) {
                uint32_t t[4];
                ldmat4(t, sb + 32768 + tswz(brow + nt4 * 16, e));
                bh[nt4 * 2][0] = t[0]; bh[nt4 * 2][1] = t[2];
                bh[nt4 * 2 + 1][0] = t[1]; bh[nt4 * 2 + 1][1] = t[3];
            }
            #pragma unroll
            for (int mt = 0; mt < 4; mt++)
                #pragma unroll
                for (int nt = 0; nt < 8; nt++)
                    mma16816(acc[mt][nt], ah[mt], bh[nt]);

            {
                uint32_t al[4][4];
                #pragma unroll
                for (int mt = 0; mt < 4; mt++)
                    ldmat4(al[mt], sb + 16384 + tswz(arow + mt * 16, e));
                #pragma unroll
                for (int mt = 0; mt < 4; mt++)
                    #pragma unroll
                    for (int nt = 0; nt < 8; nt++)
                        mma16816(acc[mt][nt], al[mt], bh[nt]);
            }
            {
                uint32_t bl[8][2];
                #pragma unroll
                for (int nt4 = 0; nt4 < 4; nt4++) {
                    uint32_t t[4];
                    ldmat4(t, sb + 40960 + tswz(brow + nt4 * 16, e));
                    bl[nt4 * 2][0] = t[0]; bl[nt4 * 2][1] = t[2];
                    bl[nt4 * 2 + 1][0] = t[1]; bl[nt4 * 2 + 1][1] = t[3];
                }
                #pragma unroll
                for (int mt = 0; mt < 4; mt++)
                    #pragma unroll
                    for (int nt = 0; nt < 8; nt++)
                        mma16816(acc[mt][nt], ah[mt], bl[nt]);
            }
        }
        __syncthreads();
        if (kc + 2 < cpp) issue(kc + 2);
        cp_commit();
    }

    const float RS = 0.70710678118654752f;

    if (MODE != 3) {
        const long r0 = bm + wm * 64 + (lane >> 2);
        const long c0 = bn + wn * 64 + (lane & 3) * 2;
        #pragma unroll
        for (int mt = 0; mt < 4; mt++) {
            #pragma unroll
            for (int h = 0; h < 2; h++) {
                long row = r0 + mt * 16 + h * 8;
                #pragma unroll
                for (int nt = 0; nt < 8; nt++) {
                    long col = c0 + nt * 8;
                    float v0 = acc[mt][nt][h * 2], v1 = acc[mt][nt][h * 2 + 1];
                    if (MODE == 0) {
                        float* C = (float*)C0v + coff;
                        float2 v; v.x = v0; v.y = v1;
                        *(float2*)(C + row * (long)ldc + col) = v;
                    } else if (MODE == 1) {
                        __nv_bfloat16* Ch = (__nv_bfloat16*)C0v + coff;
                        __nv_bfloat16* Cl = (__nv_bfloat16*)C1v + coff;
                        __nv_bfloat162 hi, lo;
                        split2(v0, v1, hi, lo);
                        *(__nv_bfloat162*)(Ch + row * (long)ldc + col) = hi;
                        *(__nv_bfloat162*)(Cl + row * (long)ldc + col) = lo;
                    } else {  // MODE 2
                        float* C = (float*)C0v + coff;
                        float2 x = *(const float2*)(X + row * (long)ldx + col);
                        float2 v;
                        v.x = (v0 + x.x) * RS; v.y = (v1 + x.y) * RS;
                        *(float2*)(C + row * (long)ldc + col) = v;
                    }
                }
            }
        }
    } else {
        // MODE 3: stage 128-row halves in smem, emit coalesced 16B stores.
        // Output: vt[((b*8+head)*128 + d)*1024 + s], head fixed per CTA.
        float* stg = (float*)smp;   // [128][129] fp32 = 66048 B
        const int head = (int)(bn >> 7);
        const long b = bm >> 10;
        const long s0 = bm & 1023;
        __nv_bfloat16* Ch = (__nv_bfloat16*)C0v;
        __nv_bfloat16* Cl = (__nv_bfloat16*)C1v;
        #pragma unroll
        for (int half = 0; half < 2; ++half) {
            __syncthreads();
            if ((wm >> 1) == half) {
                int sr0 = wm * 64 - half * 128 + (lane >> 2);
                int sc0 = wn * 64 + (lane & 3) * 2;
                #pragma unroll
                for (int mt = 0; mt < 4; mt++)
                    #pragma unroll
                    for (int h = 0; h < 2; h++) {
                        int sr = sr0 + mt * 16 + h * 8;
                        #pragma unroll
                        for (int nt = 0; nt < 8; nt++) {
                            int scc = sc0 + nt * 8;
                            stg[sr * 129 + scc]     = acc[mt][nt][h * 2];
                            stg[sr * 129 + scc + 1] = acc[mt][nt][h * 2 + 1];
                        }
                    }
            }
            __syncthreads();
            #pragma unroll
            for (int t = 0; t < 8; ++t) {
                int task = t * 256 + tid;
                int d = task >> 4;
                int sseg = task & 15;
                __nv_bfloat162 hi[4], lo[4];
                #pragma unroll
                for (int i = 0; i < 4; ++i) {
                    float x = stg[(sseg * 8 + 2 * i) * 129 + d];
                    float y = stg[(sseg * 8 + 2 * i + 1) * 129 + d];
                    split2(x, y, hi[i], lo[i]);
                }
                long basei = (((b << 3) + head) * 128 + d) * 1024
                             + s0 + half * 128 + sseg * 8;
                *(uint4*)(Ch + basei) = *(uint4*)hi;
                *(uint4*)(Cl + basei) = *(uint4*)lo;
            }
        }
    }
}

// ===========================================================================
// Softmax: softmax(v*alpha + bias) per row, fp32 in -> split bf16 planes out
// ===========================================================================
__global__ void softmax_kernel(const float* __restrict__ sc,
                               const float* __restrict__ bias) {
    long row = blockIdx.x;
    const float4* p = (const float4*)(sc + row * (long)SS);
    const float4* bp = (const float4*)(bias + (row & (long)(HH * SS - 1)) * SS);
    const float alpha = 0.08838834764831845f;  // 1/sqrt(128)
    __shared__ float red[256];
    int t = threadIdx.x;
    float4 v = p[t];
    float4 b4 = bp[t];
    v.x = v.x * alpha + b4.x; v.y = v.y * alpha + b4.y;
    v.z = v.z * alpha + b4.z; v.w = v.w * alpha + b4.w;
    float mx = fmaxf(fmaxf(v.x, v.y), fmaxf(v.z, v.w));
    red[t] = mx; __syncthreads();
    for (int o = 128; o > 0; o >>= 1) {
        if (t < o) red[t] = fmaxf(red[t], red[t + o]);
        __syncthreads();
    }
    float m = red[0];
    __syncthreads();
    v.x = __expf(v.x - m); v.y = __expf(v.y - m);
    v.z = __expf(v.z - m); v.w = __expf(v.w - m);
    float s = v.x + v.y + v.z + v.w;
    red[t] = s; __syncthreads();
    for (int o = 128; o > 0; o >>= 1) {
        if (t < o) red[t] += red[t + o];
        __syncthreads();
    }
    float inv = 1.0f / red[0];
    v.x *= inv; v.y *= inv; v.z *= inv; v.w *= inv;
    long i = row * (long)SS + t * 4;
    __nv_bfloat162 h0, l0, h1, l1;
    split2(v.x, v.y, h0, l0);
    split2(v.z, v.w, h1, l1);
    *(__nv_bfloat162*)(g_ah + i) = h0; *(__nv_bfloat162*)(g_ah + i + 2) = h1;
    *(__nv_bfloat162*)(g_al + i) = l0; *(__nv_bfloat162*)(g_al + i + 2) = l1;
}

// ===========================================================================
// Launch
// ===========================================================================
extern "C" void kernel_launch(void* const* d_in, const int* in_sizes, int n_in,
                              void* d_out, int out_size) {
    const float* query  = (const float*)d_in[0];
    const float* gain_s = (const float*)d_in[1];
    // d_in[2] = gain_t (unused: time_dim=0)
    const float* qw = (const float*)d_in[3];
    const float* kw = (const float*)d_in[4];
    const float* vw = (const float*)d_in[5];
    const float* ow = (const float*)d_in[6];
    const float* bias = (const float*)d_in[7];
    float* out = (float*)d_out;

    __nv_bfloat16 *wnh, *wnl, *xh, *xl, *ph, *pl, *vth, *vtl, *ah, *al, *ovh, *ovl;
    float *sc;
    cudaGetSymbolAddress((void**)&wnh, g_wnh); cudaGetSymbolAddress((void**)&wnl, g_wnl);
    cudaGetSymbolAddress((void**)&xh,  g_xh);  cudaGetSymbolAddress((void**)&xl,  g_xl);
    cudaGetSymbolAddress((void**)&ph,  g_ph);  cudaGetSymbolAddress((void**)&pl,  g_pl);
    cudaGetSymbolAddress((void**)&vth, g_vth); cudaGetSymbolAddress((void**)&vtl, g_vtl);
    cudaGetSymbolAddress((void**)&ah,  g_ah);  cudaGetSymbolAddress((void**)&al,  g_al);
    cudaGetSymbolAddress((void**)&ovh, g_ovh); cudaGetSymbolAddress((void**)&ovl, g_ovl);
    cudaGetSymbolAddress((void**)&sc,  g_sc);

    cudaFuncSetAttribute(mma_gemm<0>, cudaFuncAttributeMaxDynamicSharedMemorySize, SMEM_BYTES);
    cudaFuncSetAttribute(mma_gemm<1>, cudaFuncAttributeMaxDynamicSharedMemorySize, SMEM_BYTES);
    cudaFuncSetAttribute(mma_gemm<2>, cudaFuncAttributeMaxDynamicSharedMemorySize, SMEM_BYTES);
    cudaFuncSetAttribute(mma_gemm<3>, cudaFuncAttributeMaxDynamicSharedMemorySize, SMEM_BYTES);

    // 1. Normalize weights -> split planes; convert query -> split planes
    norm_w_kernel<<<dim3(EE, 4), 256>>>(qw, kw, vw, ow, gain_s);
    convert_x_kernel<<<(long)MM * EE / 1024, 256>>>(query);

    // 2a. Q,K projections -> split planes (z: 0=Q, 1=K)
    mma_gemm<1><<<dim3(EE/128, MM/256, 2), 256, SMEM_BYTES>>>(
        xh, xl, 0, 0, EE,
        wnh, wnl, (long)EE*EE, 0, EE,
        ph, pl, (long)MM*EE, 0, EE,
        nullptr, 0, EE, 1);

    // 2b. V projection -> transposed split planes vt[b][h][d][s]
    mma_gemm<3><<<dim3(EE/128, MM/256, 1), 256, SMEM_BYTES>>>(
        xh, xl, 0, 0, EE,
        wnh + 2L*EE*EE, wnl + 2L*EE*EE, 0, 0, EE,
        vth, vtl, 0, 0, 0,
        nullptr, 0, EE, 1);

    // 3. raw scores = Q @ K^T (fp32; scale+bias deferred to softmax)
    mma_gemm<0><<<dim3(SS/128, SS/256, BB*HH), 256, SMEM_BYTES>>>(
        ph, pl, (long)SS*EE, (long)HD, EE,
        ph + (long)MM*EE, pl + (long)MM*EE, (long)SS*EE, (long)HD, EE,
        sc, nullptr, (long)HH*SS*SS, (long)SS*SS, SS,
        nullptr, 0, HD, HH);

    // 4. softmax(v/sqrt(hd) + bias) -> attn split planes
    softmax_kernel<<<BB*HH*SS, 256>>>(sc, bias);

    // 5. O = attn @ V -> split planes (A: [s][t], B: vt [d][t], N=128)
    mma_gemm<1><<<dim3(1, SS/256, BB*HH), 256, SMEM_BYTES>>>(
        ah, al, (long)HH*SS*SS, (long)SS*SS, SS,
        vth, vtl, (long)HH*HD*SS, (long)HD*SS, SS,
        ovh, ovl, (long)SS*EE, (long)HD, EE,
        nullptr, 0, SS, HH);

    // 6. out = (query + OV @ wn_o^T) / sqrt(2)
    mma_gemm<2><<<dim3(EE/128, MM/256, 1), 256, SMEM_BYTES>>>(
        ovh, ovl, 0, 0, EE,
        wnh + 3L*EE*EE, wnl + 3L*EE*EE, 0, 0, EE,
        out, nullptr, 0, 0, EE,
        query, EE, EE, 1);
}

// round 9
// speedup vs baseline: 1.0055x; 1.0055x over previous
#include <cuda_runtime.h>
#include <cuda_bf16.h>
#include <cstdint>
#include <math.h>

#define BB 8
#define SS 1024
#define EE 1024
#define HH 8
#define HD 128
#define MM (BB*SS)

// Scratch (allocation-free: __device__ globals), all split-bf16 hi/lo planes
__device__ __nv_bfloat16 g_wnh[4L * EE * EE], g_wnl[4L * EE * EE]; // weights
__device__ __nv_bfloat16 g_xh[(long)MM * EE], g_xl[(long)MM * EE]; // query
__device__ __nv_bfloat16 g_ph[2L * MM * EE],  g_pl[2L * MM * EE];  // Q,K
__device__ __nv_bfloat16 g_vth[(long)MM * EE], g_vtl[(long)MM * EE]; // V^T
__device__ __nv_bfloat16 g_ovh[(long)MM * EE], g_ovl[(long)MM * EE]; // attn out

// ===========================================================================
// helpers
// ===========================================================================
__device__ __forceinline__ uint32_t smem_u32(const void* p) {
    uint32_t a;
    asm("{ .reg .u64 t; cvta.to.shared.u64 t, %1; cvt.u32.u64 %0, t; }"
        : "=r"(a) : "l"(p));
    return a;
}
__device__ __forceinline__ void ldmat4(uint32_t* r, uint32_t addr) {
    asm volatile("ldmatrix.sync.aligned.m8n8.x4.shared.b16 {%0,%1,%2,%3}, [%4];"
                 : "=r"(r[0]), "=r"(r[1]), "=r"(r[2]), "=r"(r[3]) : "r"(addr));
}
__device__ __forceinline__ void mma16816(float* c, const uint32_t* a, const uint32_t* b) {
    asm volatile(
        "mma.sync.aligned.m16n8k16.row.col.f32.bf16.bf16.f32 "
        "{%0,%1,%2,%3}, {%4,%5,%6,%7}, {%8,%9}, {%0,%1,%2,%3};"
        : "+f"(c[0]), "+f"(c[1]), "+f"(c[2]), "+f"(c[3])
        : "r"(a[0]), "r"(a[1]), "r"(a[2]), "r"(a[3]), "r"(b[0]), "r"(b[1]));
}
__device__ __forceinline__ void cpa16(uint32_t dst, const void* src) {
    asm volatile("cp.async.cg.shared.global [%0], [%1], 16;"
                 :: "r"(dst), "l"(src) : "memory");
}
__device__ __forceinline__ void cp_commit() {
    asm volatile("cp.async.commit_group;" ::: "memory");
}
template<int N>
__device__ __forceinline__ void cp_wait() {
    asm volatile("cp.async.wait_group %0;" :: "n"(N) : "memory");
}
__device__ __forceinline__ void split2(float x, float y,
                                       __nv_bfloat162& hi, __nv_bfloat162& lo) {
    hi.x = __float2bfloat16(x); hi.y = __float2bfloat16(y);
    lo.x = __float2bfloat16(x - __bfloat162float(hi.x));
    lo.y = __float2bfloat16(y - __bfloat162float(hi.y));
}

// swizzled byte offset of (row, elem) in packed [rows][32] bf16 plane (GEMM)
__device__ __forceinline__ uint32_t tswz(int r, int e) {
    return (uint32_t)(r * 64 + ((((e >> 3) ^ (r >> 1)) & 3) << 4) + (e & 7) * 2);
}
// swizzled byte offset of (row, elem) in packed [rows][128] bf16 plane (flash)
// FIX (R8 bug): XOR with (r&7) only — preserves bit 3 of the 4-bit chunk
// index so all 16 chunks of the 256B row are addressable (was &7 after XOR
// with full r, aliasing chunks 8..15 onto 0..7 and destroying data).
__device__ __forceinline__ uint32_t sw128(int r, int e) {
    return (uint32_t)(r * 256 + (((e >> 3) ^ (r & 7)) << 4) + ((e & 7) << 1));
}

// ===========================================================================
// Weight normalization -> split bf16 planes
// ===========================================================================
__global__ void norm_w_kernel(const float* __restrict__ qw,
                              const float* __restrict__ kw,
                              const float* __restrict__ vw,
                              const float* __restrict__ ow,
                              const float* __restrict__ gain) {
    int mat = blockIdx.y;
    int row = blockIdx.x;
    const float* w = (mat == 0) ? qw : (mat == 1) ? kw : (mat == 2) ? vw : ow;
    const float* wr = w + (long)row * EE;
    __shared__ float red[256];
    float s = 0.f;
    for (int i = threadIdx.x; i < EE; i += 256) { float v = wr[i]; s += v * v; }
    red[threadIdx.x] = s; __syncthreads();
    for (int o = 128; o > 0; o >>= 1) {
        if (threadIdx.x < o) red[threadIdx.x] += red[threadIdx.x + o];
        __syncthreads();
    }
    float n = sqrtf(red[0]);
    float scale = gain[0] / (32.0f * 1e-4f + n);
    long base = (long)mat * EE * EE + (long)row * EE;
    for (int i = threadIdx.x * 2; i < EE; i += 512) {
        __nv_bfloat162 hi, lo;
        split2(wr[i] * scale, wr[i + 1] * scale, hi, lo);
        *(__nv_bfloat162*)(g_wnh + base + i) = hi;
        *(__nv_bfloat162*)(g_wnl + base + i) = lo;
    }
}

// ===========================================================================
// query fp32 -> split bf16 planes
// ===========================================================================
__global__ void convert_x_kernel(const float* __restrict__ x) {
    long i = ((long)blockIdx.x * 256 + threadIdx.x) * 4;
    float4 v = *(const float4*)(x + i);
    __nv_bfloat162 h0, l0, h1, l1;
    split2(v.x, v.y, h0, l0);
    split2(v.z, v.w, h1, l1);
    *(__nv_bfloat162*)(g_xh + i) = h0; *(__nv_bfloat162*)(g_xh + i + 2) = h1;
    *(__nv_bfloat162*)(g_xl + i) = l0; *(__nv_bfloat162*)(g_xl + i + 2) = l1;
}

// ===========================================================================
// bf16 split GEMM (R6 config): CTA 128x128, 8 warps (4x2) of 32x64, BK=32,
// 3-stage cp.async, 2 CTAs/SM.
// MODE 1: split write hi/lo bf16 planes
// MODE 2: C0 = (acc + X) / sqrt(2), fp32
// MODE 3: transpose split write vt[b][h][d][s], smem-staged coalesced
// ===========================================================================
#define STG_BYTES 32768           // 4 planes x 8KB
#define SMEM_BYTES (3*STG_BYTES)  // 98304

template<int MODE>
__global__ __launch_bounds__(256, 2) void mma_gemm(
    const __nv_bfloat16* __restrict__ Ah, const __nv_bfloat16* __restrict__ Al,
    long sA1, long sA2, int lda,
    const __nv_bfloat16* __restrict__ Bh, const __nv_bfloat16* __restrict__ Bl,
    long sB1, long sB2, int ldb,
    void* C0v, void* C1v, long sC1, long sC2, int ldc,
    const float* __restrict__ X, int ldx,
    int Kr, int zdiv)
{
    extern __shared__ char smp[];
    const uint32_t smb = smem_u32(smp);

    const int tid = threadIdx.x;
    const int lane = tid & 31, wid = tid >> 5;
    const int wm = wid & 3, wn = wid >> 2;

    int z = blockIdx.z;
    int zb = z / zdiv, zh = z - zb * zdiv;
    Ah += zb * sA1 + zh * sA2;  Al += zb * sA1 + zh * sA2;
    Bh += zb * sB1 + zh * sB2;  Bl += zb * sB1 + zh * sB2;
    const long coff = zb * sC1 + zh * sC2;
    const long bm = (long)blockIdx.y * 128;
    const long bn = (long)blockIdx.x * 128;

    const int lrow = tid >> 1;
    const int lc0 = (tid & 1) * 2;
    const uint32_t lsw = (uint32_t)((lrow >> 1) & 3);
    const uint32_t lso = (uint32_t)(lrow * 64);

    const __nv_bfloat16* gAh = Ah + (bm + lrow) * (long)lda;
    const __nv_bfloat16* gAl = Al + (bm + lrow) * (long)lda;
    const __nv_bfloat16* gBh = Bh + (bn + lrow) * (long)ldb;
    const __nv_bfloat16* gBl = Bl + (bn + lrow) * (long)ldb;

    float acc[2][8][4];
    #pragma unroll
    for (int i = 0; i < 2; i++)
        #pragma unroll
        for (int j = 0; j < 8; j++)
            #pragma unroll
            for (int q = 0; q < 4; q++) acc[i][j][q] = 0.f;

    const int cpp = Kr >> 5;

    auto issue = [&](int chunk) {
        const uint32_t base = smb + (chunk % 3) * STG_BYTES;
        const int k0 = chunk << 5;
        #pragma unroll
        for (int j = 0; j < 2; j++) {
            int c = lc0 + j;
            uint32_t off = lso + (((uint32_t)c ^ lsw) << 4);
            cpa16(base + off,         gAh + k0 + c * 8);
            cpa16(base + 8192 + off,  gAl + k0 + c * 8);
            cpa16(base + 16384 + off, gBh + k0 + c * 8);
            cpa16(base + 24576 + off, gBl + k0 + c * 8);
        }
    };

    issue(0); cp_commit();
    if (cpp > 1) issue(1);
    cp_commit();

    const int r16 = lane & 15, kh8 = (lane >> 4) * 8;
    const int arow = wm * 32 + r16;
    const int brow = wn * 64 + r16;

    for (int kc = 0; kc < cpp; ++kc) {
        cp_wait<1>();
        __syncthreads();
        if (kc + 2 < cpp) issue(kc + 2);
        cp_commit();

        const uint32_t sb = smb + (kc % 3) * STG_BYTES;
        #pragma unroll
        for (int k16 = 0; k16 < 32; k16 += 16) {
            const int e = k16 + kh8;
            uint32_t ah[2][4], bh[8][2];
            #pragma unroll
            for (int mt = 0; mt < 2; mt++)
                ldmat4(ah[mt], sb + tswz(arow + mt * 16, e));
            #pragma unroll
            for (int nt4 = 0; nt4 < 4; nt4++) {
                uint32_t t[4];
                ldmat4(t, sb + 16384 + tswz(brow + nt4 * 16, e));
                bh[nt4 * 2][0] = t[0]; bh[nt4 * 2][1] = t[2];
                bh[nt4 * 2 + 1][0] = t[1]; bh[nt4 * 2 + 1][1] = t[3];
            }
            #pragma unroll
            for (int mt = 0; mt < 2; mt++)
                #pragma unroll
                for (int nt = 0; nt < 8; nt++)
                    mma16816(acc[mt][nt], ah[mt], bh[nt]);

            {
                uint32_t al[2][4];
                #pragma unroll
                for (int mt = 0; mt < 2; mt++)
                    ldmat4(al[mt], sb + 8192 + tswz(arow + mt * 16, e));
                #pragma unroll
                for (int mt = 0; mt < 2; mt++)
                    #pragma unroll
                    for (int nt = 0; nt < 8; nt++)
                        mma16816(acc[mt][nt], al[mt], bh[nt]);
            }
            {
                uint32_t bl[8][2];
                #pragma unroll
                for (int nt4 = 0; nt4 < 4; nt4++) {
                    uint32_t t[4];
                    ldmat4(t, sb + 24576 + tswz(brow + nt4 * 16, e));
                    bl[nt4 * 2][0] = t[0]; bl[nt4 * 2][1] = t[2];
                    bl[nt4 * 2 + 1][0] = t[1]; bl[nt4 * 2 + 1][1] = t[3];
                }
                #pragma unroll
                for (int mt = 0; mt < 2; mt++)
                    #pragma unroll
                    for (int nt = 0; nt < 8; nt++)
                        mma16816(acc[mt][nt], ah[mt], bl[nt]);
            }
        }
        __syncthreads();
    }

    const float RS = 0.70710678118654752f;

    if (MODE != 3) {
        const long r0 = bm + wm * 32 + (lane >> 2);
        const long c0 = bn + wn * 64 + (lane & 3) * 2;
        #pragma unroll
        for (int mt = 0; mt < 2; mt++) {
            #pragma unroll
            for (int h = 0; h < 2; h++) {
                long row = r0 + mt * 16 + h * 8;
                #pragma unroll
                for (int nt = 0; nt < 8; nt++) {
                    long col = c0 + nt * 8;
                    float v0 = acc[mt][nt][h * 2], v1 = acc[mt][nt][h * 2 + 1];
                    if (MODE == 1) {
                        __nv_bfloat16* Ch = (__nv_bfloat16*)C0v + coff;
                        __nv_bfloat16* Cl = (__nv_bfloat16*)C1v + coff;
                        __nv_bfloat162 hi, lo;
                        split2(v0, v1, hi, lo);
                        *(__nv_bfloat162*)(Ch + row * (long)ldc + col) = hi;
                        *(__nv_bfloat162*)(Cl + row * (long)ldc + col) = lo;
                    } else {  // MODE 2
                        float* C = (float*)C0v + coff;
                        float2 x = *(const float2*)(X + row * (long)ldx + col);
                        float2 v;
                        v.x = (v0 + x.x) * RS; v.y = (v1 + x.y) * RS;
                        *(float2*)(C + row * (long)ldc + col) = v;
                    }
                }
            }
        }
    } else {
        // MODE 3: stage full 128x128 tile in smem, coalesced 16B stores.
        float* stg = (float*)smp;   // [128][129] fp32 = 66048 B <= 98304
        const int sr0 = wm * 32 + (lane >> 2);
        const int sc0 = wn * 64 + (lane & 3) * 2;
        #pragma unroll
        for (int mt = 0; mt < 2; mt++)
            #pragma unroll
            for (int h = 0; h < 2; h++) {
                int sr = sr0 + mt * 16 + h * 8;
                #pragma unroll
                for (int nt = 0; nt < 8; nt++) {
                    int scc = sc0 + nt * 8;
                    stg[sr * 129 + scc]     = acc[mt][nt][h * 2];
                    stg[sr * 129 + scc + 1] = acc[mt][nt][h * 2 + 1];
                }
            }
        __syncthreads();
        const int head = (int)(bn >> 7);
        const long b = bm >> 10, s0 = bm & 1023;
        __nv_bfloat16* Ch = (__nv_bfloat16*)C0v;
        __nv_bfloat16* Cl = (__nv_bfloat16*)C1v;
        #pragma unroll
        for (int t = 0; t < 8; ++t) {
            int task = t * 256 + tid;
            int d = task >> 4;
            int seg = task & 15;
            __nv_bfloat162 hi[4], lo[4];
            #pragma unroll
            for (int i = 0; i < 4; ++i) {
                float x = stg[(seg * 8 + 2 * i) * 129 + d];
                float y = stg[(seg * 8 + 2 * i + 1) * 129 + d];
                split2(x, y, hi[i], lo[i]);
            }
            long basei = (((b << 3) + head) * 128 + d) * 1024 + s0 + seg * 8;
            *(uint4*)(Ch + basei) = *(uint4*)hi;
            *(uint4*)(Cl + basei) = *(uint4*)lo;
        }
    }
}

// ===========================================================================
// Fused flash attention: per CTA = 64 q-rows x 1 head.
// Q resident in smem; K/V tiles (128) via cp.async; online softmax with
// fused scale+bias; P split hi/lo through smem; O accumulated fp32.
// Output: split bf16 planes (ovh/ovl) for the O-projection.
// ===========================================================================
#define QT 64
#define KT 128
#define FNIT (SS/KT)

#define OQ    0
#define OKV0  32768
#define OKV1  98304
#define OBIAS 163840
#define OP    196608
#define ORED  229376
#define FSMEM 231424

__global__ __launch_bounds__(256, 1) void flash_attn(
    const __nv_bfloat16* __restrict__ ph, const __nv_bfloat16* __restrict__ pl,
    const __nv_bfloat16* __restrict__ vth, const __nv_bfloat16* __restrict__ vtl,
    const float* __restrict__ bias,
    __nv_bfloat16* __restrict__ ovh, __nv_bfloat16* __restrict__ ovl)
{
    extern __shared__ char sm[];
    const uint32_t smb = smem_u32(sm);
    const int tid = threadIdx.x, lane = tid & 31, wid = tid >> 5;
    const int wm = wid & 1, wn = wid >> 1;      // warps 2x4
    const int qt = blockIdx.x, bh = blockIdx.y;
    const int b = bh >> 3, h = bh & 7;

    const long q0 = (long)b * SS + (long)qt * QT;
    const __nv_bfloat16* Qh = ph + q0 * EE + h * HD;
    const __nv_bfloat16* Ql = pl + q0 * EE + h * HD;
    const __nv_bfloat16* Kh = ph + (long)MM * EE + (long)b * SS * EE + h * HD;
    const __nv_bfloat16* Kl = pl + (long)MM * EE + (long)b * SS * EE + h * HD;
    const __nv_bfloat16* Vh = vth + (long)bh * HD * SS;
    const __nv_bfloat16* Vl = vtl + (long)bh * HD * SS;
    const float* Bp = bias + (long)h * SS * SS + ((long)qt * QT) * SS;

    auto issueQ = [&]() {
        int r = tid >> 2, cb = (tid & 3) * 4;
        #pragma unroll
        for (int i = 0; i < 4; i++) {
            int c = cb + i;
            cpa16(smb + OQ + sw128(r, c * 8),         Qh + (long)r * EE + c * 8);
            cpa16(smb + OQ + 16384 + sw128(r, c * 8), Ql + (long)r * EE + c * 8);
        }
    };
    auto issueK = [&](int j) {
        int r = tid >> 1, cb = (tid & 1) * 8;
        #pragma unroll
        for (int i = 0; i < 8; i++) {
            int c = cb + i;
            cpa16(smb + OKV0 + sw128(r, c * 8),
                  Kh + (long)(j * KT + r) * EE + c * 8);
            cpa16(smb + OKV0 + 32768 + sw128(r, c * 8),
                  Kl + (long)(j * KT + r) * EE + c * 8);
        }
    };
    auto issueV = [&](int j) {
        int r = tid >> 1, cb = (tid & 1) * 8;
        #pragma unroll
        for (int i = 0; i < 8; i++) {
            int c = cb + i;
            cpa16(smb + OKV1 + sw128(r, c * 8),
                  Vh + (long)r * SS + j * KT + c * 8);
            cpa16(smb + OKV1 + 32768 + sw128(r, c * 8),
                  Vl + (long)r * SS + j * KT + c * 8);
        }
    };
    auto issueB = [&](int j) {
        int r = tid >> 2, cb = (tid & 3) * 8;
        #pragma unroll
        for (int i = 0; i < 8; i++) {
            int c = cb + i;
            cpa16(smb + OBIAS + r * 512 + c * 16,
                  Bp + (long)r * SS + j * KT + c * 4);
        }
    };

    issueQ(); issueK(0); cp_commit();
    issueV(0); issueB(0); cp_commit();

    float acco[2][4][4];
    #pragma unroll
    for (int i = 0; i < 2; i++)
        #pragma unroll
        for (int j = 0; j < 4; j++)
            #pragma unroll
            for (int q = 0; q < 4; q++) acco[i][j][q] = 0.f;
    float mrun[2][2] = {{-1e30f, -1e30f}, {-1e30f, -1e30f}};
    float lrun[2][2] = {{0.f, 0.f}, {0.f, 0.f}};

    const int r16 = lane & 15, kh8 = (lane >> 4) * 8;
    const int rr = lane >> 2, qc = (lane & 3) * 2;
    float* redM = (float*)(sm + ORED);
    float* redS = redM + 256;
    const float alpha = 0.08838834764831845f;   // 1/sqrt(128)

    for (int j = 0; j < FNIT; ++j) {
        // ---- wait for K_j ----
        if (j == 0) cp_wait<1>(); else cp_wait<2>();
        __syncthreads();

        // ---- S = Q K^T (3-pass split) ----
        float accs[2][4][4];
        #pragma unroll
        for (int i = 0; i < 2; i++)
            #pragma unroll
            for (int n = 0; n < 4; n++)
                #pragma unroll
                for (int q = 0; q < 4; q++) accs[i][n][q] = 0.f;

        #pragma unroll
        for (int k16 = 0; k16 < 8; ++k16) {
            const int e = k16 * 16 + kh8;
            uint32_t qh[2][4], kh[4][2];
            #pragma unroll
            for (int mt = 0; mt < 2; mt++)
                ldmat4(qh[mt], smb + OQ + sw128(wm * 32 + mt * 16 + r16, e));
            #pragma unroll
            for (int nt16 = 0; nt16 < 2; nt16++) {
                uint32_t t[4];
                ldmat4(t, smb + OKV0 + sw128(wn * 32 + nt16 * 16 + r16, e));
                kh[nt16 * 2][0] = t[0]; kh[nt16 * 2][1] = t[2];
                kh[nt16 * 2 + 1][0] = t[1]; kh[nt16 * 2 + 1][1] = t[3];
            }
            #pragma unroll
            for (int mt = 0; mt < 2; mt++)
                #pragma unroll
                for (int nt = 0; nt < 4; nt++)
                    mma16816(accs[mt][nt], qh[mt], kh[nt]);
            {
                uint32_t ql[2][4];
                #pragma unroll
                for (int mt = 0; mt < 2; mt++)
                    ldmat4(ql[mt], smb + OQ + 16384 + sw128(wm * 32 + mt * 16 + r16, e));
                #pragma unroll
                for (int mt = 0; mt < 2; mt++)
                    #pragma unroll
                    for (int nt = 0; nt < 4; nt++)
                        mma16816(accs[mt][nt], ql[mt], kh[nt]);
            }
            {
                uint32_t kl[4][2];
                #pragma unroll
                for (int nt16 = 0; nt16 < 2; nt16++) {
                    uint32_t t[4];
                    ldmat4(t, smb + OKV0 + 32768 + sw128(wn * 32 + nt16 * 16 + r16, e));
                    kl[nt16 * 2][0] = t[0]; kl[nt16 * 2][1] = t[2];
                    kl[nt16 * 2 + 1][0] = t[1]; kl[nt16 * 2 + 1][1] = t[3];
                }
                #pragma unroll
                for (int mt = 0; mt < 2; mt++)
                    #pragma unroll
                    for (int nt = 0; nt < 4; nt++)
                        mma16816(accs[mt][nt], qh[mt], kl[nt]);
            }
        }
        __syncthreads();
        if (j + 1 < FNIT) issueK(j + 1);
        cp_commit();
        cp_wait<1>();          // V_j + bias_j done (K_{j+1} may pend)
        __syncthreads();

        // ---- scale + bias, online softmax ----
        #pragma unroll
        for (int mt = 0; mt < 2; mt++)
            #pragma unroll
            for (int hh = 0; hh < 2; hh++) {
                int row = wm * 32 + mt * 16 + hh * 8 + rr;
                float mloc = -1e30f;
                #pragma unroll
                for (int nt = 0; nt < 4; nt++) {
                    int col = wn * 32 + nt * 8 + qc;
                    float2 bv = *(float2*)(sm + OBIAS + row * 512 + col * 4);
                    float s0 = accs[mt][nt][hh * 2]     * alpha + bv.x;
                    float s1 = accs[mt][nt][hh * 2 + 1] * alpha + bv.y;
                    accs[mt][nt][hh * 2] = s0; accs[mt][nt][hh * 2 + 1] = s1;
                    mloc = fmaxf(mloc, fmaxf(s0, s1));
                }
                mloc = fmaxf(mloc, __shfl_xor_sync(0xffffffffu, mloc, 1));
                mloc = fmaxf(mloc, __shfl_xor_sync(0xffffffffu, mloc, 2));
                if ((lane & 3) == 0) redM[row * 4 + wn] = mloc;
            }
        __syncthreads();
        #pragma unroll
        for (int mt = 0; mt < 2; mt++)
            #pragma unroll
            for (int hh = 0; hh < 2; hh++) {
                int row = wm * 32 + mt * 16 + hh * 8 + rr;
                float mx = fmaxf(fmaxf(redM[row * 4], redM[row * 4 + 1]),
                                 fmaxf(redM[row * 4 + 2], redM[row * 4 + 3]));
                float mnew = fmaxf(mrun[mt][hh], mx);
                float scale = __expf(mrun[mt][hh] - mnew);
                mrun[mt][hh] = mnew;
                float ssum = 0.f;
                #pragma unroll
                for (int nt = 0; nt < 4; nt++) {
                    float p0 = __expf(accs[mt][nt][hh * 2]     - mnew);
                    float p1 = __expf(accs[mt][nt][hh * 2 + 1] - mnew);
                    accs[mt][nt][hh * 2] = p0; accs[mt][nt][hh * 2 + 1] = p1;
                    ssum += p0 + p1;
                    acco[mt][nt][hh * 2]     *= scale;
                    acco[mt][nt][hh * 2 + 1] *= scale;
                }
                ssum += __shfl_xor_sync(0xffffffffu, ssum, 1);
                ssum += __shfl_xor_sync(0xffffffffu, ssum, 2);
                lrun[mt][hh] *= scale;
                if ((lane & 3) == 0) redS[row * 4 + wn] = ssum;
            }
        __syncthreads();
        #pragma unroll
        for (int mt = 0; mt < 2; mt++)
            #pragma unroll
            for (int hh = 0; hh < 2; hh++) {
                int row = wm * 32 + mt * 16 + hh * 8 + rr;
                lrun[mt][hh] += redS[row * 4] + redS[row * 4 + 1]
                              + redS[row * 4 + 2] + redS[row * 4 + 3];
                // write P split planes
                #pragma unroll
                for (int nt = 0; nt < 4; nt++) {
                    int col = wn * 32 + nt * 8 + qc;
                    __nv_bfloat162 hi, lo;
                    split2(accs[mt][nt][hh * 2], accs[mt][nt][hh * 2 + 1], hi, lo);
                    uint32_t so = sw128(row, col);
                    *(__nv_bfloat162*)(sm + OP + so) = hi;
                    *(__nv_bfloat162*)(sm + OP + 16384 + so) = lo;
                }
            }
        __syncthreads();
        if (j + 1 < FNIT) issueB(j + 1);
        cp_commit();

        // ---- O += P V (3-pass split) ----
        #pragma unroll
        for (int k16 = 0; k16 < 8; ++k16) {
            const int e = k16 * 16 + kh8;
            uint32_t pf[2][4], vh[4][2];
            #pragma unroll
            for (int mt = 0; mt < 2; mt++)
                ldmat4(pf[mt], smb + OP + sw128(wm * 32 + mt * 16 + r16, e));
            #pragma unroll
            for (int nt16 = 0; nt16 < 2; nt16++) {
                uint32_t t[4];
                ldmat4(t, smb + OKV1 + sw128(wn * 32 + nt16 * 16 + r16, e));
                vh[nt16 * 2][0] = t[0]; vh[nt16 * 2][1] = t[2];
                vh[nt16 * 2 + 1][0] = t[1]; vh[nt16 * 2 + 1][1] = t[3];
            }
            #pragma unroll
            for (int mt = 0; mt < 2; mt++)
                #pragma unroll
                for (int nt = 0; nt < 4; nt++)
                    mma16816(acco[mt][nt], pf[mt], vh[nt]);
            {
                uint32_t pl2[2][4];
                #pragma unroll
                for (int mt = 0; mt < 2; mt++)
                    ldmat4(pl2[mt], smb + OP + 16384 + sw128(wm * 32 + mt * 16 + r16, e));
                #pragma unroll
                for (int mt = 0; mt < 2; mt++)
                    #pragma unroll
                    for (int nt = 0; nt < 4; nt++)
                        mma16816(acco[mt][nt], pl2[mt], vh[nt]);
            }
            {
                uint32_t vl[4][2];
                #pragma unroll
                for (int nt16 = 0; nt16 < 2; nt16++) {
                    uint32_t t[4];
                    ldmat4(t, smb + OKV1 + 32768 + sw128(wn * 32 + nt16 * 16 + r16, e));
                    vl[nt16 * 2][0] = t[0]; vl[nt16 * 2][1] = t[2];
                    vl[nt16 * 2 + 1][0] = t[1]; vl[nt16 * 2 + 1][1] = t[3];
                }
                #pragma unroll
                for (int mt = 0; mt < 2; mt++)
                    #pragma unroll
                    for (int nt = 0; nt < 4; nt++)
                        mma16816(acco[mt][nt], pf[mt], vl[nt]);
            }
        }
        __syncthreads();
        if (j + 1 < FNIT) issueV(j + 1);
        cp_commit();
    }

    // ---- epilogue: O / l -> split planes ----
    #pragma unroll
    for (int mt = 0; mt < 2; mt++)
        #pragma unroll
        for (int hh = 0; hh < 2; hh++) {
            int rowl = wm * 32 + mt * 16 + hh * 8 + rr;
            float inv = 1.0f / lrun[mt][hh];
            long grow = q0 + rowl;
            #pragma unroll
            for (int nt = 0; nt < 4; nt++) {
                int col = h * HD + wn * 32 + nt * 8 + qc;
                float o0 = acco[mt][nt][hh * 2] * inv;
                float o1 = acco[mt][nt][hh * 2 + 1] * inv;
                __nv_bfloat162 hi, lo;
                split2(o0, o1, hi, lo);
                *(__nv_bfloat162*)(ovh + grow * EE + col) = hi;
                *(__nv_bfloat162*)(ovl + grow * EE + col) = lo;
            }
        }
}

// ===========================================================================
// Launch
// ===========================================================================
extern "C" void kernel_launch(void* const* d_in, const int* in_sizes, int n_in,
                              void* d_out, int out_size) {
    const float* query  = (const float*)d_in[0];
    const float* gain_s = (const float*)d_in[1];
    // d_in[2] = gain_t (unused: time_dim=0)
    const float* qw = (const float*)d_in[3];
    const float* kw = (const float*)d_in[4];
    const float* vw = (const float*)d_in[5];
    const float* ow = (const float*)d_in[6];
    const float* bias = (const float*)d_in[7];
    float* out = (float*)d_out;

    __nv_bfloat16 *wnh, *wnl, *xh, *xl, *ph, *pl, *vth, *vtl, *ovh, *ovl;
    cudaGetSymbolAddress((void**)&wnh, g_wnh); cudaGetSymbolAddress((void**)&wnl, g_wnl);
    cudaGetSymbolAddress((void**)&xh,  g_xh);  cudaGetSymbolAddress((void**)&xl,  g_xl);
    cudaGetSymbolAddress((void**)&ph,  g_ph);  cudaGetSymbolAddress((void**)&pl,  g_pl);
    cudaGetSymbolAddress((void**)&vth, g_vth); cudaGetSymbolAddress((void**)&vtl, g_vtl);
    cudaGetSymbolAddress((void**)&ovh, g_ovh); cudaGetSymbolAddress((void**)&ovl, g_ovl);

    cudaFuncSetAttribute(mma_gemm<1>, cudaFuncAttributeMaxDynamicSharedMemorySize, SMEM_BYTES);
    cudaFuncSetAttribute(mma_gemm<2>, cudaFuncAttributeMaxDynamicSharedMemorySize, SMEM_BYTES);
    cudaFuncSetAttribute(mma_gemm<3>, cudaFuncAttributeMaxDynamicSharedMemorySize, SMEM_BYTES);
    cudaFuncSetAttribute(flash_attn, cudaFuncAttributeMaxDynamicSharedMemorySize, FSMEM);

    // 1. Normalize weights -> split planes; convert query -> split planes
    norm_w_kernel<<<dim3(EE, 4), 256>>>(qw, kw, vw, ow, gain_s);
    convert_x_kernel<<<(long)MM * EE / 1024, 256>>>(query);

    // 2a. Q,K projections -> split planes (z: 0=Q, 1=K)
    mma_gemm<1><<<dim3(EE/128, MM/128, 2), 256, SMEM_BYTES>>>(
        xh, xl, 0, 0, EE,
        wnh, wnl, (long)EE*EE, 0, EE,
        ph, pl, (long)MM*EE, 0, EE,
        nullptr, 0, EE, 1);

    // 2b. V projection -> transposed split planes vt[b][h][d][s]
    mma_gemm<3><<<dim3(EE/128, MM/128, 1), 256, SMEM_BYTES>>>(
        xh, xl, 0, 0, EE,
        wnh + 2L*EE*EE, wnl + 2L*EE*EE, 0, 0, EE,
        vth, vtl, 0, 0, 0,
        nullptr, 0, EE, 1);

    // 3. fused attention: scores + bias + softmax + @V in one kernel
    flash_attn<<<dim3(SS/QT, BB*HH), 256, FSMEM>>>(
        ph, pl, vth, vtl, bias, ovh, ovl);

    // 4. out = (query + OV @ wn_o^T) / sqrt(2)
    mma_gemm<2><<<dim3(EE/128, MM/128, 1), 256, SMEM_BYTES>>>(
        ovh, ovl, 0, 0, EE,
        wnh + 3L*EE*EE, wnl + 3L*EE*EE, 0, 0, EE,
        out, nullptr, 0, 0, EE,
        query, EE, EE, 1);
}

// round 10
// speedup vs baseline: 1.0766x; 1.0708x over previous
#include <cuda_runtime.h>
#include <cuda_bf16.h>
#include <cstdint>
#include <math.h>

#define BB 8
#define SS 1024
#define EE 1024
#define HH 8
#define HD 128
#define MM (BB*SS)

// Scratch (allocation-free: __device__ globals), all split-bf16 hi/lo planes
__device__ __nv_bfloat16 g_wnh[4L * EE * EE], g_wnl[4L * EE * EE]; // weights
__device__ __nv_bfloat16 g_xh[(long)MM * EE], g_xl[(long)MM * EE]; // query
__device__ __nv_bfloat16 g_ph[3L * MM * EE],  g_pl[3L * MM * EE];  // Q,K,V
__device__ float g_sc[(long)BB * HH * SS * SS];                    // scores fp32
__device__ __nv_bfloat16 g_ah[(long)BB * HH * SS * SS];            // attn hi
__device__ __nv_bfloat16 g_al[(long)BB * HH * SS * SS];            // attn lo
__device__ __nv_bfloat16 g_ovh[(long)MM * EE], g_ovl[(long)MM * EE]; // attn out

// ===========================================================================
// helpers
// ===========================================================================
__device__ __forceinline__ uint32_t smem_u32(const void* p) {
    uint32_t a;
    asm("{ .reg .u64 t; cvta.to.shared.u64 t, %1; cvt.u32.u64 %0, t; }"
        : "=r"(a) : "l"(p));
    return a;
}
__device__ __forceinline__ void ldmat4(uint32_t* r, uint32_t addr) {
    asm volatile("ldmatrix.sync.aligned.m8n8.x4.shared.b16 {%0,%1,%2,%3}, [%4];"
                 : "=r"(r[0]), "=r"(r[1]), "=r"(r[2]), "=r"(r[3]) : "r"(addr));
}
__device__ __forceinline__ void ldmat4t(uint32_t* r, uint32_t addr) {
    asm volatile("ldmatrix.sync.aligned.m8n8.x4.trans.shared.b16 {%0,%1,%2,%3}, [%4];"
                 : "=r"(r[0]), "=r"(r[1]), "=r"(r[2]), "=r"(r[3]) : "r"(addr));
}
__device__ __forceinline__ void mma16816(float* c, const uint32_t* a, const uint32_t* b) {
    asm volatile(
        "mma.sync.aligned.m16n8k16.row.col.f32.bf16.bf16.f32 "
        "{%0,%1,%2,%3}, {%4,%5,%6,%7}, {%8,%9}, {%0,%1,%2,%3};"
        : "+f"(c[0]), "+f"(c[1]), "+f"(c[2]), "+f"(c[3])
        : "r"(a[0]), "r"(a[1]), "r"(a[2]), "r"(a[3]), "r"(b[0]), "r"(b[1]));
}
__device__ __forceinline__ void cpa16(uint32_t dst, const void* src) {
    asm volatile("cp.async.cg.shared.global [%0], [%1], 16;"
                 :: "r"(dst), "l"(src) : "memory");
}
__device__ __forceinline__ void cp_commit() {
    asm volatile("cp.async.commit_group;" ::: "memory");
}
template<int N>
__device__ __forceinline__ void cp_wait() {
    asm volatile("cp.async.wait_group %0;" :: "n"(N) : "memory");
}
__device__ __forceinline__ void split2(float x, float y,
                                       __nv_bfloat162& hi, __nv_bfloat162& lo) {
    hi.x = __float2bfloat16(x); hi.y = __float2bfloat16(y);
    lo.x = __float2bfloat16(x - __bfloat162float(hi.x));
    lo.y = __float2bfloat16(y - __bfloat162float(hi.y));
}

// swizzled byte offset of (row, elem) in packed [rows][32] bf16 plane
__device__ __forceinline__ uint32_t tswz(int r, int e) {
    return (uint32_t)(r * 64 + ((((e >> 3) ^ (r >> 1)) & 3) << 4) + (e & 7) * 2);
}
// swizzled byte offset of (row, elem) in packed [rows][128] bf16 plane
// (XOR with r&7 only: preserves bit 3 of the 4-bit chunk index — R8 lesson)
__device__ __forceinline__ uint32_t sw128(int r, int e) {
    return (uint32_t)(r * 256 + (((e >> 3) ^ (r & 7)) << 4) + ((e & 7) << 1));
}

// ===========================================================================
// Weight normalization -> split bf16 planes
// ===========================================================================
__global__ void norm_w_kernel(const float* __restrict__ qw,
                              const float* __restrict__ kw,
                              const float* __restrict__ vw,
                              const float* __restrict__ ow,
                              const float* __restrict__ gain) {
    int mat = blockIdx.y;
    int row = blockIdx.x;
    const float* w = (mat == 0) ? qw : (mat == 1) ? kw : (mat == 2) ? vw : ow;
    const float* wr = w + (long)row * EE;
    __shared__ float red[256];
    float s = 0.f;
    for (int i = threadIdx.x; i < EE; i += 256) { float v = wr[i]; s += v * v; }
    red[threadIdx.x] = s; __syncthreads();
    for (int o = 128; o > 0; o >>= 1) {
        if (threadIdx.x < o) red[threadIdx.x] += red[threadIdx.x + o];
        __syncthreads();
    }
    float n = sqrtf(red[0]);
    float scale = gain[0] / (32.0f * 1e-4f + n);
    long base = (long)mat * EE * EE + (long)row * EE;
    for (int i = threadIdx.x * 2; i < EE; i += 512) {
        __nv_bfloat162 hi, lo;
        split2(wr[i] * scale, wr[i + 1] * scale, hi, lo);
        *(__nv_bfloat162*)(g_wnh + base + i) = hi;
        *(__nv_bfloat162*)(g_wnl + base + i) = lo;
    }
}

// ===========================================================================
// query fp32 -> split bf16 planes
// ===========================================================================
__global__ void convert_x_kernel(const float* __restrict__ x) {
    long i = ((long)blockIdx.x * 256 + threadIdx.x) * 4;
    float4 v = *(const float4*)(x + i);
    __nv_bfloat162 h0, l0, h1, l1;
    split2(v.x, v.y, h0, l0);
    split2(v.z, v.w, h1, l1);
    *(__nv_bfloat162*)(g_xh + i) = h0; *(__nv_bfloat162*)(g_xh + i + 2) = h1;
    *(__nv_bfloat162*)(g_xl + i) = l0; *(__nv_bfloat162*)(g_xl + i + 2) = l1;
}

// ===========================================================================
// bf16 split GEMM: CTA 128x128, 8 warps (4x2) of 32x64, BK=32,
// 3-stage cp.async, 2 CTAs/SM.
// MODE 0: C0 = acc*alpha + X, fp32           (scores + fused scale/bias)
// MODE 1: split write hi/lo bf16 planes
// MODE 2: C0 = (acc + X) / sqrt(2), fp32     (residual out)
// BNN  1: B operand stored [k][n] (NN, e.g. V[t][d]); fragments loaded via
//         ldmatrix.trans — equivalent to non-trans on [n][k] (R3 inverse).
// ===========================================================================
#define STG_BYTES 32768           // 4 planes x 8KB
#define SMEM_BYTES (3*STG_BYTES)  // 98304

template<int MODE, int BNN>
__global__ __launch_bounds__(256, 2) void mma_gemm(
    const __nv_bfloat16* __restrict__ Ah, const __nv_bfloat16* __restrict__ Al,
    long sA1, long sA2, int lda,
    const __nv_bfloat16* __restrict__ Bh, const __nv_bfloat16* __restrict__ Bl,
    long sB1, long sB2, int ldb,
    void* C0v, void* C1v, long sC1, long sC2, int ldc,
    const float* __restrict__ X, long sX1, long sX2, int ldx,
    int Kr, int zdiv, float alpha)
{
    extern __shared__ char smp[];
    const uint32_t smb = smem_u32(smp);

    const int tid = threadIdx.x;
    const int lane = tid & 31, wid = tid >> 5;
    const int wm = wid & 3, wn = wid >> 2;

    int z = blockIdx.z;
    int zb = z / zdiv, zh = z - zb * zdiv;
    Ah += zb * sA1 + zh * sA2;  Al += zb * sA1 + zh * sA2;
    Bh += zb * sB1 + zh * sB2;  Bl += zb * sB1 + zh * sB2;
    if (MODE == 0) X += zb * sX1 + zh * sX2;
    const long coff = zb * sC1 + zh * sC2;
    const long bm = (long)blockIdx.y * 128;
    const long bn = (long)blockIdx.x * 128;

    // A loader indices (rows of 64B)
    const int lrow = tid >> 1;
    const int lc0 = (tid & 1) * 2;
    const uint32_t lsw = (uint32_t)((lrow >> 1) & 3);
    const uint32_t lso = (uint32_t)(lrow * 64);

    const __nv_bfloat16* gAh = Ah + (bm + lrow) * (long)lda;
    const __nv_bfloat16* gAl = Al + (bm + lrow) * (long)lda;
    // K-major B loader ptrs
    const __nv_bfloat16* gBh = Bh + (bn + lrow) * (long)ldb;
    const __nv_bfloat16* gBl = Bl + (bn + lrow) * (long)ldb;
    // NN B loader indices: 32 k-rows x 128 n-cols, 16B chunks
    const int nrow = tid >> 3;            // 0..31 (k index)
    const int nc0 = (tid & 7) * 2;        // first of 2 chunks

    float acc[2][8][4];
    #pragma unroll
    for (int i = 0; i < 2; i++)
        #pragma unroll
        for (int j = 0; j < 8; j++)
            #pragma unroll
            for (int q = 0; q < 4; q++) acc[i][j][q] = 0.f;

    const int cpp = Kr >> 5;

    auto issue = [&](int chunk) {
        const uint32_t base = smb + (chunk % 3) * STG_BYTES;
        const int k0 = chunk << 5;
        #pragma unroll
        for (int j = 0; j < 2; j++) {
            int c = lc0 + j;
            uint32_t off = lso + (((uint32_t)c ^ lsw) << 4);
            cpa16(base + off,         gAh + k0 + c * 8);
            cpa16(base + 8192 + off,  gAl + k0 + c * 8);
        }
        if (BNN) {
            #pragma unroll
            for (int j = 0; j < 2; j++) {
                int c = nc0 + j;
                uint32_t off = sw128(nrow, c * 8);
                cpa16(base + 16384 + off, Bh + (long)(k0 + nrow) * ldb + bn + c * 8);
                cpa16(base + 24576 + off, Bl + (long)(k0 + nrow) * ldb + bn + c * 8);
            }
        } else {
            #pragma unroll
            for (int j = 0; j < 2; j++) {
                int c = lc0 + j;
                uint32_t off = lso + (((uint32_t)c ^ lsw) << 4);
                cpa16(base + 16384 + off, gBh + k0 + c * 8);
                cpa16(base + 24576 + off, gBl + k0 + c * 8);
            }
        }
    };

    issue(0); cp_commit();
    if (cpp > 1) issue(1);
    cp_commit();

    const int r16 = lane & 15, kh8 = (lane >> 4) * 8;
    const int arow = wm * 32 + r16;
    const int brow = wn * 64 + r16;
    // NN fragment address components
    const int nnr = (lane & 7) + ((lane >> 4) << 3);   // k row within 16
    const int nnc = lane & 8;                           // n col offset 0/8

    for (int kc = 0; kc < cpp; ++kc) {
        cp_wait<1>();
        __syncthreads();
        if (kc + 2 < cpp) issue(kc + 2);
        cp_commit();

        const uint32_t sb = smb + (kc % 3) * STG_BYTES;
        #pragma unroll
        for (int k16 = 0; k16 < 32; k16 += 16) {
            const int e = k16 + kh8;
            uint32_t ah[2][4], bh[8][2];
            #pragma unroll
            for (int mt = 0; mt < 2; mt++)
                ldmat4(ah[mt], sb + tswz(arow + mt * 16, e));
            #pragma unroll
            for (int nt4 = 0; nt4 < 4; nt4++) {
                uint32_t t[4];
                if (BNN)
                    ldmat4t(t, sb + 16384 + sw128(k16 + nnr, wn * 64 + nt4 * 16 + nnc));
                else
                    ldmat4(t, sb + 16384 + tswz(brow + nt4 * 16, e));
                bh[nt4 * 2][0] = t[0]; bh[nt4 * 2][1] = t[2];
                bh[nt4 * 2 + 1][0] = t[1]; bh[nt4 * 2 + 1][1] = t[3];
            }
            #pragma unroll
            for (int mt = 0; mt < 2; mt++)
                #pragma unroll
                for (int nt = 0; nt < 8; nt++)
                    mma16816(acc[mt][nt], ah[mt], bh[nt]);

            {
                uint32_t al[2][4];
                #pragma unroll
                for (int mt = 0; mt < 2; mt++)
                    ldmat4(al[mt], sb + 8192 + tswz(arow + mt * 16, e));
                #pragma unroll
                for (int mt = 0; mt < 2; mt++)
                    #pragma unroll
                    for (int nt = 0; nt < 8; nt++)
                        mma16816(acc[mt][nt], al[mt], bh[nt]);
            }
            {
                uint32_t bl[8][2];
                #pragma unroll
                for (int nt4 = 0; nt4 < 4; nt4++) {
                    uint32_t t[4];
                    if (BNN)
                        ldmat4t(t, sb + 24576 + sw128(k16 + nnr, wn * 64 + nt4 * 16 + nnc));
                    else
                        ldmat4(t, sb + 24576 + tswz(brow + nt4 * 16, e));
                    bl[nt4 * 2][0] = t[0]; bl[nt4 * 2][1] = t[2];
                    bl[nt4 * 2 + 1][0] = t[1]; bl[nt4 * 2 + 1][1] = t[3];
                }
                #pragma unroll
                for (int mt = 0; mt < 2; mt++)
                    #pragma unroll
                    for (int nt = 0; nt < 8; nt++)
                        mma16816(acc[mt][nt], ah[mt], bl[nt]);
            }
        }
        __syncthreads();
    }

    // epilogue
    const float RS = 0.70710678118654752f;
    const long r0 = bm + wm * 32 + (lane >> 2);
    const long c0 = bn + wn * 64 + (lane & 3) * 2;
    #pragma unroll
    for (int mt = 0; mt < 2; mt++) {
        #pragma unroll
        for (int h = 0; h < 2; h++) {
            long row = r0 + mt * 16 + h * 8;
            #pragma unroll
            for (int nt = 0; nt < 8; nt++) {
                long col = c0 + nt * 8;
                float v0 = acc[mt][nt][h * 2], v1 = acc[mt][nt][h * 2 + 1];
                if (MODE == 0) {
                    float* C = (float*)C0v + coff;
                    float2 x = *(const float2*)(X + row * (long)ldx + col);
                    float2 v;
                    v.x = v0 * alpha + x.x; v.y = v1 * alpha + x.y;
                    *(float2*)(C + row * (long)ldc + col) = v;
                } else if (MODE == 1) {
                    __nv_bfloat16* Ch = (__nv_bfloat16*)C0v + coff;
                    __nv_bfloat16* Cl = (__nv_bfloat16*)C1v + coff;
                    __nv_bfloat162 hi, lo;
                    split2(v0, v1, hi, lo);
                    *(__nv_bfloat162*)(Ch + row * (long)ldc + col) = hi;
                    *(__nv_bfloat162*)(Cl + row * (long)ldc + col) = lo;
                } else {  // MODE 2
                    float* C = (float*)C0v + coff;
                    float2 x = *(const float2*)(X + row * (long)ldx + col);
                    float2 v;
                    v.x = (v0 + x.x) * RS; v.y = (v1 + x.y) * RS;
                    *(float2*)(C + row * (long)ldc + col) = v;
                }
            }
        }
    }
}

// ===========================================================================
// Softmax: scores already scaled+biased; softmax per row -> split planes
// ===========================================================================
__global__ void softmax_kernel(const float* __restrict__ sc) {
    long row = blockIdx.x;
    const float4* p = (const float4*)(sc + row * (long)SS);
    __shared__ float red[256];
    int t = threadIdx.x;
    float4 v = p[t];
    float mx = fmaxf(fmaxf(v.x, v.y), fmaxf(v.z, v.w));
    red[t] = mx; __syncthreads();
    for (int o = 128; o > 0; o >>= 1) {
        if (t < o) red[t] = fmaxf(red[t], red[t + o]);
        __syncthreads();
    }
    float m = red[0];
    __syncthreads();
    v.x = __expf(v.x - m); v.y = __expf(v.y - m);
    v.z = __expf(v.z - m); v.w = __expf(v.w - m);
    float s = v.x + v.y + v.z + v.w;
    red[t] = s; __syncthreads();
    for (int o = 128; o > 0; o >>= 1) {
        if (t < o) red[t] += red[t + o];
        __syncthreads();
    }
    float inv = 1.0f / red[0];
    v.x *= inv; v.y *= inv; v.z *= inv; v.w *= inv;
    long i = row * (long)SS + t * 4;
    __nv_bfloat162 h0, l0, h1, l1;
    split2(v.x, v.y, h0, l0);
    split2(v.z, v.w, h1, l1);
    *(__nv_bfloat162*)(g_ah + i) = h0; *(__nv_bfloat162*)(g_ah + i + 2) = h1;
    *(__nv_bfloat162*)(g_al + i) = l0; *(__nv_bfloat162*)(g_al + i + 2) = l1;
}

// ===========================================================================
// Launch
// ===========================================================================
extern "C" void kernel_launch(void* const* d_in, const int* in_sizes, int n_in,
                              void* d_out, int out_size) {
    const float* query  = (const float*)d_in[0];
    const float* gain_s = (const float*)d_in[1];
    // d_in[2] = gain_t (unused: time_dim=0)
    const float* qw = (const float*)d_in[3];
    const float* kw = (const float*)d_in[4];
    const float* vw = (const float*)d_in[5];
    const float* ow = (const float*)d_in[6];
    const float* bias = (const float*)d_in[7];
    float* out = (float*)d_out;

    __nv_bfloat16 *wnh, *wnl, *xh, *xl, *ph, *pl, *ah, *al, *ovh, *ovl;
    float *sc;
    cudaGetSymbolAddress((void**)&wnh, g_wnh); cudaGetSymbolAddress((void**)&wnl, g_wnl);
    cudaGetSymbolAddress((void**)&xh,  g_xh);  cudaGetSymbolAddress((void**)&xl,  g_xl);
    cudaGetSymbolAddress((void**)&ph,  g_ph);  cudaGetSymbolAddress((void**)&pl,  g_pl);
    cudaGetSymbolAddress((void**)&ah,  g_ah);  cudaGetSymbolAddress((void**)&al,  g_al);
    cudaGetSymbolAddress((void**)&ovh, g_ovh); cudaGetSymbolAddress((void**)&ovl, g_ovl);
    cudaGetSymbolAddress((void**)&sc,  g_sc);

    cudaFuncSetAttribute((const void*)&mma_gemm<0,0>, cudaFuncAttributeMaxDynamicSharedMemorySize, SMEM_BYTES);
    cudaFuncSetAttribute((const void*)&mma_gemm<1,0>, cudaFuncAttributeMaxDynamicSharedMemorySize, SMEM_BYTES);
    cudaFuncSetAttribute((const void*)&mma_gemm<1,1>, cudaFuncAttributeMaxDynamicSharedMemorySize, SMEM_BYTES);
    cudaFuncSetAttribute((const void*)&mma_gemm<2,0>, cudaFuncAttributeMaxDynamicSharedMemorySize, SMEM_BYTES);

    // 1. Normalize weights -> split planes; convert query -> split planes
    norm_w_kernel<<<dim3(EE, 4), 256>>>(qw, kw, vw, ow, gain_s);
    convert_x_kernel<<<(long)MM * EE / 1024, 256>>>(query);

    // 2. Q,K,V projections -> split planes (z: 0=Q, 1=K, 2=V; token-major)
    mma_gemm<1,0><<<dim3(EE/128, MM/128, 3), 256, SMEM_BYTES>>>(
        xh, xl, 0, 0, EE,
        wnh, wnl, (long)EE*EE, 0, EE,
        ph, pl, (long)MM*EE, 0, EE,
        nullptr, 0, 0, 0, EE, 1, 1.0f);

    // 3. scores = Q @ K^T * alpha + bias (fp32), z = b*H + h
    mma_gemm<0,0><<<dim3(SS/128, SS/128, BB*HH), 256, SMEM_BYTES>>>(
        ph, pl, (long)SS*EE, (long)HD, EE,
        ph + (long)MM*EE, pl + (long)MM*EE, (long)SS*EE, (long)HD, EE,
        sc, nullptr, (long)HH*SS*SS, (long)SS*SS, SS,
        bias, 0, (long)SS*SS, SS,
        HD, HH, 0.08838834764831845f);

    // 4. softmax -> attn split planes
    softmax_kernel<<<BB*HH*SS, 256>>>(sc);

    // 5. O = attn @ V (B = V[t][d] NN layout via trans ldmatrix)
    mma_gemm<1,1><<<dim3(1, SS/128, BB*HH), 256, SMEM_BYTES>>>(
        ah, al, (long)HH*SS*SS, (long)SS*SS, SS,
        ph + 2L*MM*EE, pl + 2L*MM*EE, (long)SS*EE, (long)HD, EE,
        ovh, ovl, (long)SS*EE, (long)HD, EE,
        nullptr, 0, 0, 0,
        SS, HH, 1.0f);

    // 6. out = (query + OV @ wn_o^T) / sqrt(2)
    mma_gemm<2,0><<<dim3(EE/128, MM/128, 1), 256, SMEM_BYTES>>>(
        ovh, ovl, 0, 0, EE,
        wnh + 3L*EE*EE, wnl + 3L*EE*EE, 0, 0, EE,
        out, nullptr, 0, 0, EE,
        query, 0, 0, EE,
        EE, 1, 1.0f);
}

// round 11
// speedup vs baseline: 1.1430x; 1.0616x over previous
#include <cuda_runtime.h>
#include <cuda_bf16.h>
#include <cstdint>
#include <math.h>

#define BB 8
#define SS 1024
#define EE 1024
#define HH 8
#define HD 128
#define MM (BB*SS)

// Scratch (allocation-free: __device__ globals), all split-bf16 hi/lo planes
__device__ __nv_bfloat16 g_wnh[4L * EE * EE], g_wnl[4L * EE * EE]; // weights
__device__ __nv_bfloat16 g_xh[(long)MM * EE], g_xl[(long)MM * EE]; // query
__device__ __nv_bfloat16 g_ph[3L * MM * EE],  g_pl[3L * MM * EE];  // Q,K,V
__device__ float g_sc[(long)BB * HH * SS * SS];                    // scores fp32
__device__ __nv_bfloat16 g_ah[(long)BB * HH * SS * SS];            // attn hi
__device__ __nv_bfloat16 g_al[(long)BB * HH * SS * SS];            // attn lo
__device__ __nv_bfloat16 g_ovh[(long)MM * EE], g_ovl[(long)MM * EE]; // attn out

// ===========================================================================
// helpers
// ===========================================================================
__device__ __forceinline__ uint32_t smem_u32(const void* p) {
    uint32_t a;
    asm("{ .reg .u64 t; cvta.to.shared.u64 t, %1; cvt.u32.u64 %0, t; }"
        : "=r"(a) : "l"(p));
    return a;
}
__device__ __forceinline__ void ldmat4(uint32_t* r, uint32_t addr) {
    asm volatile("ldmatrix.sync.aligned.m8n8.x4.shared.b16 {%0,%1,%2,%3}, [%4];"
                 : "=r"(r[0]), "=r"(r[1]), "=r"(r[2]), "=r"(r[3]) : "r"(addr));
}
__device__ __forceinline__ void ldmat4t(uint32_t* r, uint32_t addr) {
    asm volatile("ldmatrix.sync.aligned.m8n8.x4.trans.shared.b16 {%0,%1,%2,%3}, [%4];"
                 : "=r"(r[0]), "=r"(r[1]), "=r"(r[2]), "=r"(r[3]) : "r"(addr));
}
__device__ __forceinline__ void mma16816(float* c, const uint32_t* a, const uint32_t* b) {
    asm volatile(
        "mma.sync.aligned.m16n8k16.row.col.f32.bf16.bf16.f32 "
        "{%0,%1,%2,%3}, {%4,%5,%6,%7}, {%8,%9}, {%0,%1,%2,%3};"
        : "+f"(c[0]), "+f"(c[1]), "+f"(c[2]), "+f"(c[3])
        : "r"(a[0]), "r"(a[1]), "r"(a[2]), "r"(a[3]), "r"(b[0]), "r"(b[1]));
}
__device__ __forceinline__ void cpa16(uint32_t dst, const void* src) {
    asm volatile("cp.async.cg.shared.global [%0], [%1], 16;"
                 :: "r"(dst), "l"(src) : "memory");
}
__device__ __forceinline__ void cp_commit() {
    asm volatile("cp.async.commit_group;" ::: "memory");
}
template<int N>
__device__ __forceinline__ void cp_wait() {
    asm volatile("cp.async.wait_group %0;" :: "n"(N) : "memory");
}
__device__ __forceinline__ void split2(float x, float y,
                                       __nv_bfloat162& hi, __nv_bfloat162& lo) {
    hi.x = __float2bfloat16(x); hi.y = __float2bfloat16(y);
    lo.x = __float2bfloat16(x - __bfloat162float(hi.x));
    lo.y = __float2bfloat16(y - __bfloat162float(hi.y));
}

// swizzled byte offset of (row, elem) in packed [rows][32] bf16 plane
__device__ __forceinline__ uint32_t tswz(int r, int e) {
    return (uint32_t)(r * 64 + ((((e >> 3) ^ (r >> 1)) & 3) << 4) + (e & 7) * 2);
}
// swizzled byte offset of (row, elem) in packed [rows][128] bf16 plane
// (XOR with r&7 only: preserves bit 3 of the 4-bit chunk index — R8 lesson)
__device__ __forceinline__ uint32_t sw128(int r, int e) {
    return (uint32_t)(r * 256 + (((e >> 3) ^ (r & 7)) << 4) + ((e & 7) << 1));
}

// ===========================================================================
// Weight normalization -> split bf16 planes
// ===========================================================================
__global__ void norm_w_kernel(const float* __restrict__ qw,
                              const float* __restrict__ kw,
                              const float* __restrict__ vw,
                              const float* __restrict__ ow,
                              const float* __restrict__ gain) {
    int mat = blockIdx.y;
    int row = blockIdx.x;
    const float* w = (mat == 0) ? qw : (mat == 1) ? kw : (mat == 2) ? vw : ow;
    const float* wr = w + (long)row * EE;
    __shared__ float red[256];
    float s = 0.f;
    for (int i = threadIdx.x; i < EE; i += 256) { float v = wr[i]; s += v * v; }
    red[threadIdx.x] = s; __syncthreads();
    for (int o = 128; o > 0; o >>= 1) {
        if (threadIdx.x < o) red[threadIdx.x] += red[threadIdx.x + o];
        __syncthreads();
    }
    float n = sqrtf(red[0]);
    float scale = gain[0] / (32.0f * 1e-4f + n);
    long base = (long)mat * EE * EE + (long)row * EE;
    for (int i = threadIdx.x * 2; i < EE; i += 512) {
        __nv_bfloat162 hi, lo;
        split2(wr[i] * scale, wr[i + 1] * scale, hi, lo);
        *(__nv_bfloat162*)(g_wnh + base + i) = hi;
        *(__nv_bfloat162*)(g_wnl + base + i) = lo;
    }
}

// ===========================================================================
// query fp32 -> split bf16 planes
// ===========================================================================
__global__ void convert_x_kernel(const float* __restrict__ x) {
    long i = ((long)blockIdx.x * 256 + threadIdx.x) * 4;
    float4 v = *(const float4*)(x + i);
    __nv_bfloat162 h0, l0, h1, l1;
    split2(v.x, v.y, h0, l0);
    split2(v.z, v.w, h1, l1);
    *(__nv_bfloat162*)(g_xh + i) = h0; *(__nv_bfloat162*)(g_xh + i + 2) = h1;
    *(__nv_bfloat162*)(g_xl + i) = l0; *(__nv_bfloat162*)(g_xl + i + 2) = l1;
}

// ===========================================================================
// bf16 split GEMM: CTA 128x128, 8 warps (4x2) of 32x64, BK=32,
// 3-stage cp.async, 2 CTAs/SM, SINGLE barrier per chunk (3-stage reuse
// distance makes the bottom barrier redundant — see R11 analysis).
// MODE 0: C0 = acc*alpha + X, fp32           (scores + fused scale/bias)
// MODE 1: split write hi/lo bf16 planes
// MODE 2: C0 = (acc + X) / sqrt(2), fp32     (residual out)
// BNN  1: B operand stored [k][n] (NN, e.g. V[t][d]); fragments via
//         ldmatrix.trans — equivalent to non-trans on [n][k] (R3 inverse).
// ===========================================================================
#define STG_BYTES 32768           // 4 planes x 8KB
#define SMEM_BYTES (3*STG_BYTES)  // 98304

template<int MODE, int BNN>
__global__ __launch_bounds__(256, 2) void mma_gemm(
    const __nv_bfloat16* __restrict__ Ah, const __nv_bfloat16* __restrict__ Al,
    long sA1, long sA2, int lda,
    const __nv_bfloat16* __restrict__ Bh, const __nv_bfloat16* __restrict__ Bl,
    long sB1, long sB2, int ldb,
    void* C0v, void* C1v, long sC1, long sC2, int ldc,
    const float* __restrict__ X, long sX1, long sX2, int ldx,
    int Kr, int zdiv, float alpha)
{
    extern __shared__ char smp[];
    const uint32_t smb = smem_u32(smp);

    const int tid = threadIdx.x;
    const int lane = tid & 31, wid = tid >> 5;
    const int wm = wid & 3, wn = wid >> 2;

    int z = blockIdx.z;
    int zb = z / zdiv, zh = z - zb * zdiv;
    Ah += zb * sA1 + zh * sA2;  Al += zb * sA1 + zh * sA2;
    Bh += zb * sB1 + zh * sB2;  Bl += zb * sB1 + zh * sB2;
    if (MODE == 0) X += zb * sX1 + zh * sX2;
    const long coff = zb * sC1 + zh * sC2;
    const long bm = (long)blockIdx.y * 128;
    const long bn = (long)blockIdx.x * 128;

    // A loader indices (rows of 64B)
    const int lrow = tid >> 1;
    const int lc0 = (tid & 1) * 2;
    const uint32_t lsw = (uint32_t)((lrow >> 1) & 3);
    const uint32_t lso = (uint32_t)(lrow * 64);

    const __nv_bfloat16* gAh = Ah + (bm + lrow) * (long)lda;
    const __nv_bfloat16* gAl = Al + (bm + lrow) * (long)lda;
    // K-major B loader ptrs
    const __nv_bfloat16* gBh = Bh + (bn + lrow) * (long)ldb;
    const __nv_bfloat16* gBl = Bl + (bn + lrow) * (long)ldb;
    // NN B loader indices: 32 k-rows x 128 n-cols, 16B chunks
    const int nrow = tid >> 3;            // 0..31 (k index)
    const int nc0 = (tid & 7) * 2;        // first of 2 chunks

    float acc[2][8][4];
    #pragma unroll
    for (int i = 0; i < 2; i++)
        #pragma unroll
        for (int j = 0; j < 8; j++)
            #pragma unroll
            for (int q = 0; q < 4; q++) acc[i][j][q] = 0.f;

    const int cpp = Kr >> 5;

    auto issue = [&](int chunk) {
        const uint32_t base = smb + (chunk % 3) * STG_BYTES;
        const int k0 = chunk << 5;
        #pragma unroll
        for (int j = 0; j < 2; j++) {
            int c = lc0 + j;
            uint32_t off = lso + (((uint32_t)c ^ lsw) << 4);
            cpa16(base + off,         gAh + k0 + c * 8);
            cpa16(base + 8192 + off,  gAl + k0 + c * 8);
        }
        if (BNN) {
            #pragma unroll
            for (int j = 0; j < 2; j++) {
                int c = nc0 + j;
                uint32_t off = sw128(nrow, c * 8);
                cpa16(base + 16384 + off, Bh + (long)(k0 + nrow) * ldb + bn + c * 8);
                cpa16(base + 24576 + off, Bl + (long)(k0 + nrow) * ldb + bn + c * 8);
            }
        } else {
            #pragma unroll
            for (int j = 0; j < 2; j++) {
                int c = lc0 + j;
                uint32_t off = lso + (((uint32_t)c ^ lsw) << 4);
                cpa16(base + 16384 + off, gBh + k0 + c * 8);
                cpa16(base + 24576 + off, gBl + k0 + c * 8);
            }
        }
    };

    issue(0); cp_commit();
    if (cpp > 1) issue(1);
    cp_commit();

    const int r16 = lane & 15, kh8 = (lane >> 4) * 8;
    const int arow = wm * 32 + r16;
    const int brow = wn * 64 + r16;
    // NN fragment address components
    const int nnr = (lane & 7) + ((lane >> 4) << 3);   // k row within 16
    const int nnc = lane & 8;                           // n col offset 0/8

    for (int kc = 0; kc < cpp; ++kc) {
        cp_wait<1>();
        __syncthreads();   // single barrier per chunk (reuse distance = 3 stages)
        if (kc + 2 < cpp) issue(kc + 2);
        cp_commit();

        const uint32_t sb = smb + (kc % 3) * STG_BYTES;
        #pragma unroll
        for (int k16 = 0; k16 < 32; k16 += 16) {
            const int e = k16 + kh8;
            uint32_t ah[2][4], bh[8][2];
            #pragma unroll
            for (int mt = 0; mt < 2; mt++)
                ldmat4(ah[mt], sb + tswz(arow + mt * 16, e));
            #pragma unroll
            for (int nt4 = 0; nt4 < 4; nt4++) {
                uint32_t t[4];
                if (BNN)
                    ldmat4t(t, sb + 16384 + sw128(k16 + nnr, wn * 64 + nt4 * 16 + nnc));
                else
                    ldmat4(t, sb + 16384 + tswz(brow + nt4 * 16, e));
                bh[nt4 * 2][0] = t[0]; bh[nt4 * 2][1] = t[2];
                bh[nt4 * 2 + 1][0] = t[1]; bh[nt4 * 2 + 1][1] = t[3];
            }
            #pragma unroll
            for (int mt = 0; mt < 2; mt++)
                #pragma unroll
                for (int nt = 0; nt < 8; nt++)
                    mma16816(acc[mt][nt], ah[mt], bh[nt]);

            {
                uint32_t al[2][4];
                #pragma unroll
                for (int mt = 0; mt < 2; mt++)
                    ldmat4(al[mt], sb + 8192 + tswz(arow + mt * 16, e));
                #pragma unroll
                for (int mt = 0; mt < 2; mt++)
                    #pragma unroll
                    for (int nt = 0; nt < 8; nt++)
                        mma16816(acc[mt][nt], al[mt], bh[nt]);
            }
            {
                uint32_t bl[8][2];
                #pragma unroll
                for (int nt4 = 0; nt4 < 4; nt4++) {
                    uint32_t t[4];
                    if (BNN)
                        ldmat4t(t, sb + 24576 + sw128(k16 + nnr, wn * 64 + nt4 * 16 + nnc));
                    else
                        ldmat4(t, sb + 24576 + tswz(brow + nt4 * 16, e));
                    bl[nt4 * 2][0] = t[0]; bl[nt4 * 2][1] = t[2];
                    bl[nt4 * 2 + 1][0] = t[1]; bl[nt4 * 2 + 1][1] = t[3];
                }
                #pragma unroll
                for (int mt = 0; mt < 2; mt++)
                    #pragma unroll
                    for (int nt = 0; nt < 8; nt++)
                        mma16816(acc[mt][nt], ah[mt], bl[nt]);
            }
        }
    }

    // epilogue
    const float RS = 0.70710678118654752f;
    const long r0 = bm + wm * 32 + (lane >> 2);
    const long c0 = bn + wn * 64 + (lane & 3) * 2;
    #pragma unroll
    for (int mt = 0; mt < 2; mt++) {
        #pragma unroll
        for (int h = 0; h < 2; h++) {
            long row = r0 + mt * 16 + h * 8;
            #pragma unroll
            for (int nt = 0; nt < 8; nt++) {
                long col = c0 + nt * 8;
                float v0 = acc[mt][nt][h * 2], v1 = acc[mt][nt][h * 2 + 1];
                if (MODE == 0) {
                    float* C = (float*)C0v + coff;
                    float2 x = *(const float2*)(X + row * (long)ldx + col);
                    float2 v;
                    v.x = v0 * alpha + x.x; v.y = v1 * alpha + x.y;
                    *(float2*)(C + row * (long)ldc + col) = v;
                } else if (MODE == 1) {
                    __nv_bfloat16* Ch = (__nv_bfloat16*)C0v + coff;
                    __nv_bfloat16* Cl = (__nv_bfloat16*)C1v + coff;
                    __nv_bfloat162 hi, lo;
                    split2(v0, v1, hi, lo);
                    *(__nv_bfloat162*)(Ch + row * (long)ldc + col) = hi;
                    *(__nv_bfloat162*)(Cl + row * (long)ldc + col) = lo;
                } else {  // MODE 2
                    float* C = (float*)C0v + coff;
                    float2 x = *(const float2*)(X + row * (long)ldx + col);
                    float2 v;
                    v.x = (v0 + x.x) * RS; v.y = (v1 + x.y) * RS;
                    *(float2*)(C + row * (long)ldc + col) = v;
                }
            }
        }
    }
}

// ===========================================================================
// Softmax: warp-per-row, register-resident, shfl reductions, no barriers.
// Scores already scaled+biased. Writes split bf16 planes.
// ===========================================================================
__global__ void softmax_kernel(const float* __restrict__ sc) {
    const long row = (long)blockIdx.x * 8 + (threadIdx.x >> 5);
    const int lane = threadIdx.x & 31;
    const float4* p = (const float4*)(sc + row * (long)SS);

    float4 v[8];
    float mx = -1e30f;
    #pragma unroll
    for (int j = 0; j < 8; j++) {
        v[j] = p[j * 32 + lane];
        mx = fmaxf(mx, fmaxf(fmaxf(v[j].x, v[j].y), fmaxf(v[j].z, v[j].w)));
    }
    #pragma unroll
    for (int o = 16; o > 0; o >>= 1)
        mx = fmaxf(mx, __shfl_xor_sync(0xffffffffu, mx, o));

    float s = 0.f;
    #pragma unroll
    for (int j = 0; j < 8; j++) {
        v[j].x = __expf(v[j].x - mx); v[j].y = __expf(v[j].y - mx);
        v[j].z = __expf(v[j].z - mx); v[j].w = __expf(v[j].w - mx);
        s += v[j].x + v[j].y + v[j].z + v[j].w;
    }
    #pragma unroll
    for (int o = 16; o > 0; o >>= 1)
        s += __shfl_xor_sync(0xffffffffu, s, o);
    const float inv = 1.0f / s;

    #pragma unroll
    for (int j = 0; j < 8; j++) {
        long i = row * (long)SS + (j * 32 + lane) * 4;
        __nv_bfloat162 h0, l0, h1, l1;
        split2(v[j].x * inv, v[j].y * inv, h0, l0);
        split2(v[j].z * inv, v[j].w * inv, h1, l1);
        *(__nv_bfloat162*)(g_ah + i) = h0; *(__nv_bfloat162*)(g_ah + i + 2) = h1;
        *(__nv_bfloat162*)(g_al + i) = l0; *(__nv_bfloat162*)(g_al + i + 2) = l1;
    }
}

// ===========================================================================
// Launch
// ===========================================================================
extern "C" void kernel_launch(void* const* d_in, const int* in_sizes, int n_in,
                              void* d_out, int out_size) {
    const float* query  = (const float*)d_in[0];
    const float* gain_s = (const float*)d_in[1];
    // d_in[2] = gain_t (unused: time_dim=0)
    const float* qw = (const float*)d_in[3];
    const float* kw = (const float*)d_in[4];
    const float* vw = (const float*)d_in[5];
    const float* ow = (const float*)d_in[6];
    const float* bias = (const float*)d_in[7];
    float* out = (float*)d_out;

    __nv_bfloat16 *wnh, *wnl, *xh, *xl, *ph, *pl, *ah, *al, *ovh, *ovl;
    float *sc;
    cudaGetSymbolAddress((void**)&wnh, g_wnh); cudaGetSymbolAddress((void**)&wnl, g_wnl);
    cudaGetSymbolAddress((void**)&xh,  g_xh);  cudaGetSymbolAddress((void**)&xl,  g_xl);
    cudaGetSymbolAddress((void**)&ph,  g_ph);  cudaGetSymbolAddress((void**)&pl,  g_pl);
    cudaGetSymbolAddress((void**)&ah,  g_ah);  cudaGetSymbolAddress((void**)&al,  g_al);
    cudaGetSymbolAddress((void**)&ovh, g_ovh); cudaGetSymbolAddress((void**)&ovl, g_ovl);
    cudaGetSymbolAddress((void**)&sc,  g_sc);

    cudaFuncSetAttribute((const void*)&mma_gemm<0,0>, cudaFuncAttributeMaxDynamicSharedMemorySize, SMEM_BYTES);
    cudaFuncSetAttribute((const void*)&mma_gemm<1,0>, cudaFuncAttributeMaxDynamicSharedMemorySize, SMEM_BYTES);
    cudaFuncSetAttribute((const void*)&mma_gemm<1,1>, cudaFuncAttributeMaxDynamicSharedMemorySize, SMEM_BYTES);
    cudaFuncSetAttribute((const void*)&mma_gemm<2,0>, cudaFuncAttributeMaxDynamicSharedMemorySize, SMEM_BYTES);

    // 1. Normalize weights -> split planes; convert query -> split planes
    norm_w_kernel<<<dim3(EE, 4), 256>>>(qw, kw, vw, ow, gain_s);
    convert_x_kernel<<<(long)MM * EE / 1024, 256>>>(query);

    // 2. Q,K,V projections -> split planes (z: 0=Q, 1=K, 2=V; token-major)
    mma_gemm<1,0><<<dim3(EE/128, MM/128, 3), 256, SMEM_BYTES>>>(
        xh, xl, 0, 0, EE,
        wnh, wnl, (long)EE*EE, 0, EE,
        ph, pl, (long)MM*EE, 0, EE,
        nullptr, 0, 0, 0, EE, 1, 1.0f);

    // 3. scores = Q @ K^T * alpha + bias (fp32), z = b*H + h
    mma_gemm<0,0><<<dim3(SS/128, SS/128, BB*HH), 256, SMEM_BYTES>>>(
        ph, pl, (long)SS*EE, (long)HD, EE,
        ph + (long)MM*EE, pl + (long)MM*EE, (long)SS*EE, (long)HD, EE,
        sc, nullptr, (long)HH*SS*SS, (long)SS*SS, SS,
        bias, 0, (long)SS*SS, SS,
        HD, HH, 0.08838834764831845f);

    // 4. softmax -> attn split planes (warp-per-row)
    softmax_kernel<<<BB*HH*SS/8, 256>>>(sc);

    // 5. O = attn @ V (B = V[t][d] NN layout via trans ldmatrix)
    mma_gemm<1,1><<<dim3(1, SS/128, BB*HH), 256, SMEM_BYTES>>>(
        ah, al, (long)HH*SS*SS, (long)SS*SS, SS,
        ph + 2L*MM*EE, pl + 2L*MM*EE, (long)SS*EE, (long)HD, EE,
        ovh, ovl, (long)SS*EE, (long)HD, EE,
        nullptr, 0, 0, 0,
        SS, HH, 1.0f);

    // 6. out = (query + OV @ wn_o^T) / sqrt(2)
    mma_gemm<2,0><<<dim3(EE/128, MM/128, 1), 256, SMEM_BYTES>>>(
        ovh, ovl, 0, 0, EE,
        wnh + 3L*EE*EE, wnl + 3L*EE*EE, 0, 0, EE,
        out, nullptr, 0, 0, EE,
        query, 0, 0, EE,
        EE, 1, 1.0f);
}